// round 14
// baseline (speedup 1.0000x reference)
#include <cuda_runtime.h>

#define T_STEPS 2048
#define BATCH   256
#define D_IN    16
#define H1      5
#define H2      50
#define NC      20

__device__ __forceinline__ float tanh_fast(float x) {
    float y; asm("tanh.approx.f32 %0, %1;" : "=f"(y) : "f"(x)); return y;
}
__device__ __forceinline__ float sigmoid_fast(float x) {
    return fmaf(0.5f, tanh_fast(0.5f * x), 0.5f);
}

// One block per batch element. 256 threads = 8 warps.
//   Warps 0..6 (224 thr): layer-2. thread t -> unit u = t>>2 (0..55, 50..55 zero-padded),
//                         gate g = t&3 (0=i,1=f,2=g,3=o). Weights in registers.
//   Warp 7: layer-1. lane l -> unit l>>2 (0..7, 5..7 padded), gate l&3.
//           Lanes 0..15 also prefetch x[k+1] (warp-private double buffer, no barrier).
// After computing its gate activation, each group of 4 lanes exchanges the 4 gate
// values via shfl, updates c redundantly in-register, and lane g==0 stores h.
// Exactly ONE __syncthreads per timestep. h2 is double-buffered so the
// read(h2[prev]) / write(h2[cur]) pair is race-free under the single barrier.
// Pipeline: layer-1 produces h1[k] while layer-2 consumes h1[k-1].
__global__ __launch_bounds__(256, 2)
void lstm_fused_kernel(const float* __restrict__ x,
                       const float* __restrict__ W1ih, const float* __restrict__ W1hh,
                       const float* __restrict__ b1ih, const float* __restrict__ b1hh,
                       const float* __restrict__ W2ih, const float* __restrict__ W2hh,
                       const float* __restrict__ b2ih, const float* __restrict__ b2hh,
                       const float* __restrict__ Wfc,  const float* __restrict__ bfc,
                       float* __restrict__ out)
{
    const int b    = blockIdx.x;
    const int tid  = threadIdx.x;
    const int lane = tid & 31;
    const int wid  = tid >> 5;

    __shared__ __align__(16) float h2buf[2][56];   // double-buffered h2 (padded to 14 float4)
    __shared__ __align__(16) float h1buf[2][8];    // double-buffered h1 (padded)
    __shared__ __align__(16) float xs[2][16];      // x double buffer (warp-7 private)

    // Register weights:
    //  L2 thread: wA[0..55] = W2hh row (padded), wB[0..4] = W2ih row
    //  L1 thread: wA[0..15] = W1ih row, wA[16..20] = W1hh row
    float wA[56];
    float wB[8];
    float bias = 0.0f;
    float cst  = 0.0f;   // cell state (c2 or c1), replicated across the 4 gate lanes

    if (wid < 7) {
        const int unit = tid >> 2;
        const int g    = tid & 3;
        if (unit < H2) {
            const int row = g * H2 + unit;
            const float* wr = W2hh + row * H2;
            #pragma unroll
            for (int k = 0; k < 56; k++) wA[k] = (k < H2) ? wr[k] : 0.0f;
            const float* wi = W2ih + row * H1;
            #pragma unroll
            for (int k = 0; k < 8; k++)  wB[k] = (k < H1) ? wi[k] : 0.0f;
            bias = b2ih[row] + b2hh[row];
        } else {
            #pragma unroll
            for (int k = 0; k < 56; k++) wA[k] = 0.0f;
            #pragma unroll
            for (int k = 0; k < 8; k++)  wB[k] = 0.0f;
        }
    } else {
        const int unit = lane >> 2;
        const int g    = lane & 3;
        #pragma unroll
        for (int k = 0; k < 56; k++) wA[k] = 0.0f;
        if (unit < H1) {
            const int row = g * H1 + unit;
            #pragma unroll
            for (int k = 0; k < D_IN; k++) wA[k] = W1ih[row * D_IN + k];
            #pragma unroll
            for (int k = 0; k < H1; k++)   wA[16 + k] = W1hh[row * H1 + k];
            bias = b1ih[row] + b1hh[row];
        }
    }

    // Zero-init states / padding
    if (tid < 56) { h2buf[0][tid] = 0.0f; h2buf[1][tid] = 0.0f; }
    if (tid < 8)  { h1buf[0][tid] = 0.0f; h1buf[1][tid] = 0.0f; }
    const float* xb = x + (size_t)b * T_STEPS * D_IN;
    if (tid < 16) xs[0][tid] = xb[tid];   // x[0]
    __syncthreads();

    const unsigned FULL = 0xffffffffu;
    const int base = lane & ~3;           // lane of gate 0 in this unit's group

    for (int k = 0; k <= T_STEPS; k++) {
        const int cur  = k & 1;
        const int prev = cur ^ 1;

        if (wid < 7) {
            // ---------------- layer 2: consumes h2[prev], h1[prev] ----------------
            if (k > 0) {
                const float4* h2v = (const float4*)h2buf[prev];
                float a0 = bias, a1 = 0.0f, a2 = 0.0f, a3 = 0.0f;
                #pragma unroll
                for (int q = 0; q < 14; q += 2) {
                    float4 v = h2v[q];
                    a0 = fmaf(v.x, wA[4*q],   a0);
                    a1 = fmaf(v.y, wA[4*q+1], a1);
                    a2 = fmaf(v.z, wA[4*q+2], a2);
                    a3 = fmaf(v.w, wA[4*q+3], a3);
                }
                #pragma unroll
                for (int q = 1; q < 14; q += 2) {
                    float4 v = h2v[q];
                    a0 = fmaf(v.x, wA[4*q],   a0);
                    a1 = fmaf(v.y, wA[4*q+1], a1);
                    a2 = fmaf(v.z, wA[4*q+2], a2);
                    a3 = fmaf(v.w, wA[4*q+3], a3);
                }
                const float4 u0  = *(const float4*)h1buf[prev];
                const float  u4  = h1buf[prev][4];
                a0 = fmaf(u0.x, wB[0], a0);
                a1 = fmaf(u0.y, wB[1], a1);
                a2 = fmaf(u0.z, wB[2], a2);
                a3 = fmaf(u0.w, wB[3], a3);
                a0 = fmaf(u4,   wB[4], a0);
                const float acc = (a0 + a1) + (a2 + a3);
                const float act = ((tid & 3) == 2) ? tanh_fast(acc) : sigmoid_fast(acc);

                const float gi = __shfl_sync(FULL, act, base);
                const float gf = __shfl_sync(FULL, act, base | 1);
                const float gg = __shfl_sync(FULL, act, base | 2);
                const float go = __shfl_sync(FULL, act, base | 3);
                cst = fmaf(gf, cst, gi * gg);
                const float h = go * tanh_fast(cst);
                if ((tid & 3) == 0) h2buf[cur][tid >> 2] = h;
            }
        } else {
            // ---------------- layer 1 (warp 7): produces h1[cur] ----------------
            // prefetch x[k+1] into the other buffer (warp-private, no barrier needed)
            if (k + 1 < T_STEPS && lane < D_IN)
                xs[prev][lane] = xb[(size_t)(k + 1) * D_IN + lane];

            if (k < T_STEPS) {
                const float4* xv = (const float4*)xs[cur];
                float a0 = bias, a1 = 0.0f, a2 = 0.0f, a3 = 0.0f;
                #pragma unroll
                for (int q = 0; q < 4; q++) {
                    float4 v = xv[q];
                    a0 = fmaf(v.x, wA[4*q],   a0);
                    a1 = fmaf(v.y, wA[4*q+1], a1);
                    a2 = fmaf(v.z, wA[4*q+2], a2);
                    a3 = fmaf(v.w, wA[4*q+3], a3);
                }
                const float4 u0 = *(const float4*)h1buf[prev];
                const float  u4 = h1buf[prev][4];
                a0 = fmaf(u0.x, wA[16], a0);
                a1 = fmaf(u0.y, wA[17], a1);
                a2 = fmaf(u0.z, wA[18], a2);
                a3 = fmaf(u0.w, wA[19], a3);
                a0 = fmaf(u4,   wA[20], a0);
                const float acc = (a0 + a1) + (a2 + a3);
                const float act = ((lane & 3) == 2) ? tanh_fast(acc) : sigmoid_fast(acc);

                const float gi = __shfl_sync(FULL, act, base);
                const float gf = __shfl_sync(FULL, act, base | 1);
                const float gg = __shfl_sync(FULL, act, base | 2);
                const float go = __shfl_sync(FULL, act, base | 3);
                cst = fmaf(gf, cst, gi * gg);
                const float h = go * tanh_fast(cst);
                if ((lane & 3) == 0) h1buf[cur][lane >> 2] = h;
            }
        }
        __syncthreads();
    }

    // ---- epilogue: result = h2_last @ Wfc.T + bfc ; also emit h2_last ----
    const float* h2f = h2buf[T_STEPS & 1];
    if (tid < NC) {
        float acc = bfc[tid];
        #pragma unroll
        for (int k = 0; k < H2; k++) acc += h2f[k] * Wfc[tid * H2 + k];
        out[b * NC + tid] = acc;
    }
    if (tid >= 32 && tid < 32 + H2) {
        const int j = tid - 32;
        out[BATCH * NC + b * H2 + j] = h2f[j];
    }
}

extern "C" void kernel_launch(void* const* d_in, const int* in_sizes, int n_in,
                              void* d_out, int out_size)
{
    (void)in_sizes; (void)n_in; (void)out_size;
    const float* x    = (const float*)d_in[0];
    const float* W1ih = (const float*)d_in[1];
    const float* W1hh = (const float*)d_in[2];
    const float* b1ih = (const float*)d_in[3];
    const float* b1hh = (const float*)d_in[4];
    const float* W2ih = (const float*)d_in[5];
    const float* W2hh = (const float*)d_in[6];
    const float* b2ih = (const float*)d_in[7];
    const float* b2hh = (const float*)d_in[8];
    const float* Wfc  = (const float*)d_in[9];
    const float* bfc  = (const float*)d_in[10];

    lstm_fused_kernel<<<BATCH, 256>>>(x, W1ih, W1hh, b1ih, b1hh,
                                      W2ih, W2hh, b2ih, b2hh,
                                      Wfc, bfc, (float*)d_out);
}

// round 15
// speedup vs baseline: 1.0028x; 1.0028x over previous
#include <cuda_runtime.h>

#define T_STEPS 2048
#define BATCH   256
#define D_IN    16
#define H1      5
#define H2      50
#define NC      20

__device__ __forceinline__ float tanh_fast(float x) {
    float y; asm("tanh.approx.f32 %0, %1;" : "=f"(y) : "f"(x)); return y;
}
__device__ __forceinline__ float sigmoid_fast(float x) {
    return fmaf(0.5f, tanh_fast(0.5f * x), 0.5f);
}

// One block per batch element. 256 threads = 8 warps.
//   Warps 0..6 (224 thr): layer-2. thread t -> unit u = t>>2 (0..55, 50..55 zero-padded),
//                         gate g = t&3 (0=i,1=f,2=g,3=o). Weights in registers.
//   Warp 7: layer-1. lane l -> unit l>>2 (0..7, 5..7 padded), gate l&3.
//           Lanes 0..15 also prefetch x[k+1] (warp-private double buffer, no barrier).
// After computing its gate activation, each group of 4 lanes exchanges the 4 gate
// values via shfl, updates c redundantly in-register, and lane g==0 stores h.
// Exactly ONE __syncthreads per timestep. h2 is double-buffered so the
// read(h2[prev]) / write(h2[cur]) pair is race-free under the single barrier.
// Pipeline: layer-1 produces h1[k] while layer-2 consumes h1[k-1].
__global__ __launch_bounds__(256, 2)
void lstm_fused_kernel(const float* __restrict__ x,
                       const float* __restrict__ W1ih, const float* __restrict__ W1hh,
                       const float* __restrict__ b1ih, const float* __restrict__ b1hh,
                       const float* __restrict__ W2ih, const float* __restrict__ W2hh,
                       const float* __restrict__ b2ih, const float* __restrict__ b2hh,
                       const float* __restrict__ Wfc,  const float* __restrict__ bfc,
                       float* __restrict__ out)
{
    const int b    = blockIdx.x;
    const int tid  = threadIdx.x;
    const int lane = tid & 31;
    const int wid  = tid >> 5;

    __shared__ __align__(16) float h2buf[2][56];   // double-buffered h2 (padded to 14 float4)
    __shared__ __align__(16) float h1buf[2][8];    // double-buffered h1 (padded)
    __shared__ __align__(16) float xs[2][16];      // x double buffer (warp-7 private)

    // Register weights:
    //  L2 thread: wA[0..55] = W2hh row (padded), wB[0..4] = W2ih row
    //  L1 thread: wA[0..15] = W1ih row, wA[16..20] = W1hh row
    float wA[56];
    float wB[8];
    float bias = 0.0f;
    float cst  = 0.0f;   // cell state (c2 or c1), replicated across the 4 gate lanes

    if (wid < 7) {
        const int unit = tid >> 2;
        const int g    = tid & 3;
        if (unit < H2) {
            const int row = g * H2 + unit;
            const float* wr = W2hh + row * H2;
            #pragma unroll
            for (int k = 0; k < 56; k++) wA[k] = (k < H2) ? wr[k] : 0.0f;
            const float* wi = W2ih + row * H1;
            #pragma unroll
            for (int k = 0; k < 8; k++)  wB[k] = (k < H1) ? wi[k] : 0.0f;
            bias = b2ih[row] + b2hh[row];
        } else {
            #pragma unroll
            for (int k = 0; k < 56; k++) wA[k] = 0.0f;
            #pragma unroll
            for (int k = 0; k < 8; k++)  wB[k] = 0.0f;
        }
    } else {
        const int unit = lane >> 2;
        const int g    = lane & 3;
        #pragma unroll
        for (int k = 0; k < 56; k++) wA[k] = 0.0f;
        if (unit < H1) {
            const int row = g * H1 + unit;
            #pragma unroll
            for (int k = 0; k < D_IN; k++) wA[k] = W1ih[row * D_IN + k];
            #pragma unroll
            for (int k = 0; k < H1; k++)   wA[16 + k] = W1hh[row * H1 + k];
            bias = b1ih[row] + b1hh[row];
        }
    }

    // Zero-init states / padding
    if (tid < 56) { h2buf[0][tid] = 0.0f; h2buf[1][tid] = 0.0f; }
    if (tid < 8)  { h1buf[0][tid] = 0.0f; h1buf[1][tid] = 0.0f; }
    const float* xb = x + (size_t)b * T_STEPS * D_IN;
    if (tid < 16) xs[0][tid] = xb[tid];   // x[0]
    __syncthreads();

    const unsigned FULL = 0xffffffffu;
    const int base = lane & ~3;           // lane of gate 0 in this unit's group

    for (int k = 0; k <= T_STEPS; k++) {
        const int cur  = k & 1;
        const int prev = cur ^ 1;

        if (wid < 7) {
            // ---------------- layer 2: consumes h2[prev], h1[prev] ----------------
            if (k > 0) {
                const float4* h2v = (const float4*)h2buf[prev];
                float a0 = bias, a1 = 0.0f, a2 = 0.0f, a3 = 0.0f;
                #pragma unroll
                for (int q = 0; q < 14; q += 2) {
                    float4 v = h2v[q];
                    a0 = fmaf(v.x, wA[4*q],   a0);
                    a1 = fmaf(v.y, wA[4*q+1], a1);
                    a2 = fmaf(v.z, wA[4*q+2], a2);
                    a3 = fmaf(v.w, wA[4*q+3], a3);
                }
                #pragma unroll
                for (int q = 1; q < 14; q += 2) {
                    float4 v = h2v[q];
                    a0 = fmaf(v.x, wA[4*q],   a0);
                    a1 = fmaf(v.y, wA[4*q+1], a1);
                    a2 = fmaf(v.z, wA[4*q+2], a2);
                    a3 = fmaf(v.w, wA[4*q+3], a3);
                }
                const float4 u0  = *(const float4*)h1buf[prev];
                const float  u4  = h1buf[prev][4];
                a0 = fmaf(u0.x, wB[0], a0);
                a1 = fmaf(u0.y, wB[1], a1);
                a2 = fmaf(u0.z, wB[2], a2);
                a3 = fmaf(u0.w, wB[3], a3);
                a0 = fmaf(u4,   wB[4], a0);
                const float acc = (a0 + a1) + (a2 + a3);
                const float act = ((tid & 3) == 2) ? tanh_fast(acc) : sigmoid_fast(acc);

                const float gi = __shfl_sync(FULL, act, base);
                const float gf = __shfl_sync(FULL, act, base | 1);
                const float gg = __shfl_sync(FULL, act, base | 2);
                const float go = __shfl_sync(FULL, act, base | 3);
                cst = fmaf(gf, cst, gi * gg);
                const float h = go * tanh_fast(cst);
                if ((tid & 3) == 0) h2buf[cur][tid >> 2] = h;
            }
        } else {
            // ---------------- layer 1 (warp 7): produces h1[cur] ----------------
            // prefetch x[k+1] into the other buffer (warp-private, no barrier needed)
            if (k + 1 < T_STEPS && lane < D_IN)
                xs[prev][lane] = xb[(size_t)(k + 1) * D_IN + lane];

            if (k < T_STEPS) {
                const float4* xv = (const float4*)xs[cur];
                float a0 = bias, a1 = 0.0f, a2 = 0.0f, a3 = 0.0f;
                #pragma unroll
                for (int q = 0; q < 4; q++) {
                    float4 v = xv[q];
                    a0 = fmaf(v.x, wA[4*q],   a0);
                    a1 = fmaf(v.y, wA[4*q+1], a1);
                    a2 = fmaf(v.z, wA[4*q+2], a2);
                    a3 = fmaf(v.w, wA[4*q+3], a3);
                }
                const float4 u0 = *(const float4*)h1buf[prev];
                const float  u4 = h1buf[prev][4];
                a0 = fmaf(u0.x, wA[16], a0);
                a1 = fmaf(u0.y, wA[17], a1);
                a2 = fmaf(u0.z, wA[18], a2);
                a3 = fmaf(u0.w, wA[19], a3);
                a0 = fmaf(u4,   wA[20], a0);
                const float acc = (a0 + a1) + (a2 + a3);
                const float act = ((lane & 3) == 2) ? tanh_fast(acc) : sigmoid_fast(acc);

                const float gi = __shfl_sync(FULL, act, base);
                const float gf = __shfl_sync(FULL, act, base | 1);
                const float gg = __shfl_sync(FULL, act, base | 2);
                const float go = __shfl_sync(FULL, act, base | 3);
                cst = fmaf(gf, cst, gi * gg);
                const float h = go * tanh_fast(cst);
                if ((lane & 3) == 0) h1buf[cur][lane >> 2] = h;
            }
        }
        __syncthreads();
    }

    // ---- epilogue: result = h2_last @ Wfc.T + bfc ; also emit h2_last ----
    const float* h2f = h2buf[T_STEPS & 1];
    if (tid < NC) {
        float acc = bfc[tid];
        #pragma unroll
        for (int k = 0; k < H2; k++) acc += h2f[k] * Wfc[tid * H2 + k];
        out[b * NC + tid] = acc;
    }
    if (tid >= 32 && tid < 32 + H2) {
        const int j = tid - 32;
        out[BATCH * NC + b * H2 + j] = h2f[j];
    }
}

extern "C" void kernel_launch(void* const* d_in, const int* in_sizes, int n_in,
                              void* d_out, int out_size)
{
    (void)in_sizes; (void)n_in; (void)out_size;
    const float* x    = (const float*)d_in[0];
    const float* W1ih = (const float*)d_in[1];
    const float* W1hh = (const float*)d_in[2];
    const float* b1ih = (const float*)d_in[3];
    const float* b1hh = (const float*)d_in[4];
    const float* W2ih = (const float*)d_in[5];
    const float* W2hh = (const float*)d_in[6];
    const float* b2ih = (const float*)d_in[7];
    const float* b2hh = (const float*)d_in[8];
    const float* Wfc  = (const float*)d_in[9];
    const float* bfc  = (const float*)d_in[10];

    lstm_fused_kernel<<<BATCH, 256>>>(x, W1ih, W1hh, b1ih, b1hh,
                                      W2ih, W2hh, b2ih, b2hh,
                                      Wfc, bfc, (float*)d_out);
}